// round 1
// baseline (speedup 1.0000x reference)
#include <cuda_runtime.h>

#define FIN   64
#define FOUT  64
#define FH    128
#define LATD  512
#define NB    16
#define HW    16384
#define KTOT  53760

// weight scratch: per-sample transposed weights + biases
__device__ float g_w[NB * KTOT];

// ---------- packed f32x2 helpers ----------
__device__ __forceinline__ unsigned long long pack2f(float v) {
    unsigned long long r;
    unsigned u = __float_as_uint(v);
    asm("mov.b64 %0, {%1, %2};" : "=l"(r) : "r"(u), "r"(u));
    return r;
}
__device__ __forceinline__ void unpack2f(unsigned long long v, float& a, float& b) {
    unsigned u0, u1;
    asm("mov.b64 {%0, %1}, %2;" : "=r"(u0), "=r"(u1) : "l"(v));
    a = __uint_as_float(u0);
    b = __uint_as_float(u1);
}
__device__ __forceinline__ void ffma2(unsigned long long& d, unsigned long long a, unsigned long long b) {
    asm("fma.rn.f32x2 %0, %1, %2, %0;" : "+l"(d) : "l"(a), "l"(b));
}

// ============================================================
// Kernel A: hypernetwork GEMM  ks[b][k] = lat[b]·W[k] + bias[k]
// then scale + transpose-scatter into g_w.
// One thread per k row, 16 sample-accumulators, lat in smem.
// ============================================================
__global__ __launch_bounds__(256) void hyper_kernel(
    const float* __restrict__ lat,
    const float* __restrict__ Wm,
    const float* __restrict__ bias)
{
    __shared__ float slat[NB][LATD];   // 32 KB
    for (int i = threadIdx.x; i < NB * LATD; i += 256)
        slat[i >> 9][i & 511] = lat[i];
    __syncthreads();

    int k = blockIdx.x * 256 + threadIdx.x;   // grid 210*256 == 53760 exact

    float acc[NB];
#pragma unroll
    for (int b = 0; b < NB; b++) acc[b] = 0.f;

    const float4* wr = (const float4*)(Wm + (size_t)k * LATD);
#pragma unroll 4
    for (int l4 = 0; l4 < LATD / 4; l4++) {
        float4 w = wr[l4];
        int l = l4 * 4;
#pragma unroll
        for (int b = 0; b < NB; b++) {
            acc[b] = fmaf(w.x, slat[b][l + 0], acc[b]);
            acc[b] = fmaf(w.y, slat[b][l + 1], acc[b]);
            acc[b] = fmaf(w.z, slat[b][l + 2], acc[b]);
            acc[b] = fmaf(w.w, slat[b][l + 3], acc[b]);
        }
    }

    const float RS128 = 0.08838834764831845f;  // 1/sqrt(128)
    const float RS64  = 0.125f;                // 1/sqrt(64)

    float scale;
    int dst;
    if (k < 8192) {                       // k_in [128,64] -> [i][m]
        int m = k >> 6, i = k & 63;
        scale = RS128; dst = i * 128 + m;
    } else if (k < 24576) {               // k_mida [128,128] -> [kk][m]
        int l2 = k - 8192; int m = l2 >> 7, kk = l2 & 127;
        scale = RS128; dst = 8192 + kk * 128 + m;
    } else if (k < 40960) {               // k_midb
        int l2 = k - 24576; int m = l2 >> 7, kk = l2 & 127;
        scale = RS128; dst = 24576 + kk * 128 + m;
    } else if (k < 49152) {               // k_out [64,128] -> [kk][o]
        int l2 = k - 40960; int o = l2 >> 7, kk = l2 & 127;
        scale = RS64; dst = 40960 + kk * 64 + o;
    } else if (k < 53248) {               // k_short [64,64] -> [i][o]
        int l2 = k - 49152; int o = l2 >> 6, i = l2 & 63;
        scale = RS64; dst = 49152 + i * 64 + o;
    } else {                              // biases, unscaled, in order
        scale = 1.0f; dst = k;
    }

    float bk = bias[k];
#pragma unroll
    for (int b = 0; b < NB; b++)
        g_w[b * KTOT + dst] = (acc[b] + bk) * scale;
}

// ============================================================
// Kernel B: fused per-sample residual block over 128-pixel tiles
// ============================================================
__device__ __forceinline__ void stage(float* dst, const float* __restrict__ src,
                                      int nfloats, int tid)
{
    const float4* s = (const float4*)src;
    float4* d = (float4*)dst;
    for (int i = tid; i < nfloats / 4; i += 256) d[i] = s[i];
}

template <int TM>
__device__ __forceinline__ void init_acc(unsigned long long acc[][4],
                                         const float* __restrict__ bias_ptr, int ty)
{
#pragma unroll
    for (int m = 0; m < TM; m++) {
        unsigned long long p = pack2f(bias_ptr[ty * TM + m]);
        acc[m][0] = p; acc[m][1] = p; acc[m][2] = p; acc[m][3] = p;
    }
}

// C[MD x 128] += W[k][MD] * X[k][128]; per-thread TM x 8 tile (8 = 4 f32x2)
template <int KD, int MD, int TM>
__device__ __forceinline__ void gemm(const float* __restrict__ swp,
                                     const float* __restrict__ sin,
                                     unsigned long long acc[][4], int ty, int tx)
{
    const float* bptr = sin + tx * 8;
    const float* aptr = swp + ty * TM;
#pragma unroll 4
    for (int k = 0; k < KD; k++) {
        ulonglong2 b0 = *(const ulonglong2*)(bptr + k * 128);
        ulonglong2 b1 = *(const ulonglong2*)(bptr + k * 128 + 4);
        float4 a0 = *(const float4*)(aptr + k * MD);
        float av[TM];
        av[0] = a0.x; av[1] = a0.y; av[2] = a0.z; av[3] = a0.w;
        if constexpr (TM == 8) {
            float4 a1 = *(const float4*)(aptr + k * MD + 4);
            av[4] = a1.x; av[5] = a1.y; av[6] = a1.z; av[7] = a1.w;
        }
#pragma unroll
        for (int m = 0; m < TM; m++) {
            unsigned long long ad = pack2f(av[m]);
            ffma2(acc[m][0], ad, b0.x);
            ffma2(acc[m][1], ad, b0.y);
            ffma2(acc[m][2], ad, b1.x);
            ffma2(acc[m][3], ad, b1.y);
        }
    }
}

template <int TM, bool RELU>
__device__ __forceinline__ void store_sh(float* dst, unsigned long long acc[][4],
                                         int ty, int tx)
{
#pragma unroll
    for (int m = 0; m < TM; m++) {
        float f[8];
        unpack2f(acc[m][0], f[0], f[1]);
        unpack2f(acc[m][1], f[2], f[3]);
        unpack2f(acc[m][2], f[4], f[5]);
        unpack2f(acc[m][3], f[6], f[7]);
        if (RELU) {
#pragma unroll
            for (int j = 0; j < 8; j++) f[j] = fmaxf(f[j], 0.f);
        }
        float4* p = (float4*)(dst + (ty * TM + m) * 128 + tx * 8);
        p[0] = make_float4(f[0], f[1], f[2], f[3]);
        p[1] = make_float4(f[4], f[5], f[6], f[7]);
    }
}

__global__ __launch_bounds__(256, 1) void conv_kernel(
    const float* __restrict__ x, float* __restrict__ out)
{
    extern __shared__ float smem[];
    float* sx  = smem;            // [64][128]  = 8192 f
    float* sh1 = smem + 8192;     // [128][128] = 16384 f
    float* sh2 = smem + 24576;    // [128][128] = 16384 f
    float* sw  = smem + 40960;    // [128][128] = 16384 f (weight stage)

    int b  = blockIdx.y;
    int p0 = blockIdx.x * 128;
    int tid = threadIdx.x;
    int tx = tid & 15, ty = tid >> 4;

    const float* wbase = g_w + b * KTOT;

    // load x tile [64 ch][128 px]
    const float* xb = x + b * (FIN * HW) + p0;
#pragma unroll
    for (int j = 0; j < 8; j++) {
        int e = tid + j * 256;       // 2048 float4
        int c = e >> 5;
        int p4 = e & 31;
        ((float4*)sx)[e] = ((const float4*)(xb + c * HW))[p4];
    }
    // stage W_in^T [64][128]
    stage(sw, wbase + 0, 8192, tid);
    __syncthreads();

    unsigned long long acc[8][4];

    // ---- layer in: h1 = relu(Win @ x + b_in) ----
    init_acc<8>(acc, wbase + 53248, ty);
    gemm<64, 128, 8>(sw, sx, acc, ty, tx);
    store_sh<8, true>(sh1, acc, ty, tx);
    __syncthreads();
    stage(sw, wbase + 8192, 16384, tid);   // W_mida^T
    __syncthreads();

    // ---- layer mida ----
    init_acc<8>(acc, wbase + 53376, ty);
    gemm<128, 128, 8>(sw, sh1, acc, ty, tx);
    store_sh<8, true>(sh2, acc, ty, tx);
    __syncthreads();
    stage(sw, wbase + 24576, 16384, tid);  // W_midb^T
    __syncthreads();

    // ---- layer midb ----
    init_acc<8>(acc, wbase + 53504, ty);
    gemm<128, 128, 8>(sw, sh2, acc, ty, tx);
    store_sh<8, true>(sh1, acc, ty, tx);
    __syncthreads();
    stage(sw,        wbase + 40960, 8192, tid);  // W_out^T   [128][64]
    stage(sw + 8192, wbase + 49152, 4096, tid);  // W_short^T [64][64]
    __syncthreads();

    // ---- out layer: Wout @ h3 + Wshort @ x + b_out + b_short ----
    {
#pragma unroll
        for (int m = 0; m < 4; m++) {
            int o = ty * 4 + m;
            float bv = wbase[53632 + o] + wbase[53696 + o];
            unsigned long long p = pack2f(bv);
            acc[m][0] = p; acc[m][1] = p; acc[m][2] = p; acc[m][3] = p;
        }
        gemm<128, 64, 4>(sw, sh1, acc, ty, tx);
        gemm<64, 64, 4>(sw + 8192, sx, acc, ty, tx);

        float* ob = out + b * (FOUT * HW) + p0 + tx * 8;
#pragma unroll
        for (int m = 0; m < 4; m++) {
            int o = ty * 4 + m;
            float f[8];
            unpack2f(acc[m][0], f[0], f[1]);
            unpack2f(acc[m][1], f[2], f[3]);
            unpack2f(acc[m][2], f[4], f[5]);
            unpack2f(acc[m][3], f[6], f[7]);
            float4* p = (float4*)(ob + o * HW);
            p[0] = make_float4(f[0], f[1], f[2], f[3]);
            p[1] = make_float4(f[4], f[5], f[6], f[7]);
        }
    }
}

// ============================================================
extern "C" void kernel_launch(void* const* d_in, const int* in_sizes, int n_in,
                              void* d_out, int out_size)
{
    (void)in_sizes; (void)n_in; (void)out_size;
    const float* x    = (const float*)d_in[0];
    const float* lat  = (const float*)d_in[1];
    const float* W    = (const float*)d_in[2];
    const float* bias = (const float*)d_in[3];
    float* out = (float*)d_out;

    hyper_kernel<<<KTOT / 256, 256>>>(lat, W, bias);

    cudaFuncSetAttribute(conv_kernel,
                         cudaFuncAttributeMaxDynamicSharedMemorySize, 229376);
    dim3 grid(HW / 128, NB);
    conv_kernel<<<grid, 256, 229376>>>(x, out);
}

// round 3
// speedup vs baseline: 3.2156x; 3.2156x over previous
#include <cuda_runtime.h>
#include <cuda_bf16.h>
#include <cstdint>

#define FIN   64
#define FOUT  64
#define FH    128
#define LATD  512
#define NB    16
#define HW    16384
#define KTOT  53760
#define WS    106496   // bf16 elements of packed weights per sample

// per-sample bf16 element offsets of fragment-ordered weight buffers
#define WIN_HI   0        // O=128 I=64  (8192 ele), lo at +8192
#define WMIDA_HI 16384    // O=128 I=128 (16384),   lo at +16384
#define WMIDB_HI 49152
#define WOUT_HI  81920    // O=64 I=128  (8192),    lo at +8192
#define WSH_HI   98304    // O=64 I=64   (4096),    lo at +4096

__device__ __align__(16) __nv_bfloat16 g_wb[NB * WS];
__device__ __align__(16) float g_bias[NB * 512];

// ---------------- helpers ----------------
__device__ __forceinline__ void split2(float f0, float f1, uint32_t& hi, uint32_t& lo) {
    // hi = bf16x2(low=f0, high=f1); lo = bf16x2 of residuals
    asm("cvt.rn.bf16x2.f32 %0, %1, %2;" : "=r"(hi) : "f"(f1), "f"(f0));
    float h0 = __uint_as_float(hi << 16);
    float h1 = __uint_as_float(hi & 0xFFFF0000u);
    float r0 = f0 - h0, r1 = f1 - h1;
    asm("cvt.rn.bf16x2.f32 %0, %1, %2;" : "=r"(lo) : "f"(r1), "f"(r0));
}

__device__ __forceinline__ void mma16816(float d[4],
    uint32_t a0, uint32_t a1, uint32_t a2, uint32_t a3,
    uint32_t b0, uint32_t b1)
{
    asm volatile(
        "mma.sync.aligned.m16n8k16.row.col.f32.bf16.bf16.f32 "
        "{%0,%1,%2,%3}, {%4,%5,%6,%7}, {%8,%9}, {%0,%1,%2,%3};"
        : "+f"(d[0]), "+f"(d[1]), "+f"(d[2]), "+f"(d[3])
        : "r"(a0), "r"(a1), "r"(a2), "r"(a3), "r"(b0), "r"(b1));
}

// ============================================================
// Kernel A: hypernetwork GEMM (proven R1 core) + bf16 hi/lo pack
// into mma.sync B-fragment order.
// ============================================================
__global__ __launch_bounds__(256) void hyper_kernel(
    const float* __restrict__ lat,
    const float* __restrict__ Wm,
    const float* __restrict__ bias)
{
    __shared__ float slat[NB][LATD];   // 32 KB
    for (int i = threadIdx.x; i < NB * LATD; i += 256)
        slat[i >> 9][i & 511] = lat[i];
    __syncthreads();

    int k = blockIdx.x * 256 + threadIdx.x;   // 210*256 == 53760 exact

    float acc[NB];
#pragma unroll
    for (int s = 0; s < NB; s++) acc[s] = 0.f;

    const float4* wr = (const float4*)(Wm + (size_t)k * LATD);
#pragma unroll 4
    for (int l4 = 0; l4 < LATD / 4; l4++) {
        float4 w = wr[l4];
        int l = l4 * 4;
#pragma unroll
        for (int s = 0; s < NB; s++) {
            acc[s] = fmaf(w.x, slat[s][l + 0], acc[s]);
            acc[s] = fmaf(w.y, slat[s][l + 1], acc[s]);
            acc[s] = fmaf(w.z, slat[s][l + 2], acc[s]);
            acc[s] = fmaf(w.w, slat[s][l + 3], acc[s]);
        }
    }

    const float RS128 = 0.08838834764831845f;  // 1/sqrt(128)
    const float RS64  = 0.125f;                // 1/sqrt(64)
    float bk = bias[k];

    // map k -> (layer, o, i) -> fragment element index
    bool isBias = false;
    float scale = 1.f;
    int o = 0, i = 0, I = 0, baseHi = 0, loDelta = 0;
    if (k < 8192) {
        o = k >> 6; i = k & 63; I = 64;
        baseHi = WIN_HI; loDelta = 8192; scale = RS128;
    } else if (k < 24576) {
        int idx = k - 8192; o = idx >> 7; i = idx & 127; I = 128;
        baseHi = WMIDA_HI; loDelta = 16384; scale = RS128;
    } else if (k < 40960) {
        int idx = k - 24576; o = idx >> 7; i = idx & 127; I = 128;
        baseHi = WMIDB_HI; loDelta = 16384; scale = RS128;
    } else if (k < 49152) {
        int idx = k - 40960; o = idx >> 7; i = idx & 127; I = 128;
        baseHi = WOUT_HI; loDelta = 8192; scale = RS64;
    } else if (k < 53248) {
        int idx = k - 49152; o = idx >> 6; i = idx & 63; I = 64;
        baseHi = WSH_HI; loDelta = 4096; scale = RS64;
    } else {
        isBias = true;
    }

    int fel = 0;
    if (!isBias) {
        int KT = I / 16;
        int nt = o >> 3, kt = i >> 4;
        int tl = (o & 7) * 4 + ((i & 7) >> 1);          // lane
        int el = (((i >> 3) & 1) << 1) | (i & 1);       // elem within 4-group
        fel = baseHi + ((nt * KT + kt) * 32 + tl) * 4 + el;
    }

#pragma unroll
    for (int s = 0; s < NB; s++) {
        if (isBias) {
            g_bias[s * 512 + (k - 53248)] = acc[s] + bk;
        } else {
            float v = (acc[s] + bk) * scale;
            __nv_bfloat16 h = __float2bfloat16(v);
            __nv_bfloat16 l = __float2bfloat16(v - __bfloat162float(h));
            g_wb[(size_t)s * WS + fel]           = h;
            g_wb[(size_t)s * WS + fel + loDelta] = l;
        }
    }
}

// ============================================================
// Kernel B: mma.sync fused block; activations register-resident.
// ============================================================
// GEMM over resident fragment-ordered weights.
// D[NT][4] (+)= A[KT] x (Whi + Wlo), 3-term split.
template <int KT, int NT, bool ZERO>
__device__ __forceinline__ void layer_mma(
    float (*D)[4],
    const uint32_t (*Ahi)[4], const uint32_t (*Alo)[4],
    const char* __restrict__ sm, int hiOffB, int loOffB, int lane)
{
#pragma unroll
    for (int nt = 0; nt < NT; nt++) {
        if (ZERO) { D[nt][0] = 0.f; D[nt][1] = 0.f; D[nt][2] = 0.f; D[nt][3] = 0.f; }
#pragma unroll
        for (int kt = 0; kt < KT; kt++) {
            int fo = ((nt * KT + kt) * 32 + lane) * 8;
            uint2 bh = *(const uint2*)(sm + hiOffB + fo);
            uint2 bl = *(const uint2*)(sm + loOffB + fo);
            mma16816(D[nt], Ahi[kt][0], Ahi[kt][1], Ahi[kt][2], Ahi[kt][3], bh.x, bh.y);
            mma16816(D[nt], Alo[kt][0], Alo[kt][1], Alo[kt][2], Alo[kt][3], bh.x, bh.y);
            mma16816(D[nt], Ahi[kt][0], Ahi[kt][1], Ahi[kt][2], Ahi[kt][3], bl.x, bl.y);
        }
    }
}

// bias + relu + hi/lo split: D[2*NKT][4] -> A[NKT][4]
template <int NKT>
__device__ __forceinline__ void epi_relu_split(
    const float (*D)[4], uint32_t (*Ahi)[4], uint32_t (*Alo)[4],
    const float* __restrict__ bsm, int tig)
{
#pragma unroll
    for (int kt = 0; kt < NKT; kt++) {
#pragma unroll
        for (int half = 0; half < 2; half++) {
            int nt = 2 * kt + half;
            float b0 = bsm[nt * 8 + tig * 2];
            float b1 = bsm[nt * 8 + tig * 2 + 1];
            float v0 = fmaxf(D[nt][0] + b0, 0.f);
            float v1 = fmaxf(D[nt][1] + b1, 0.f);
            float v2 = fmaxf(D[nt][2] + b0, 0.f);
            float v3 = fmaxf(D[nt][3] + b1, 0.f);
            split2(v0, v1, Ahi[kt][half * 2 + 0], Alo[kt][half * 2 + 0]);
            split2(v2, v3, Ahi[kt][half * 2 + 1], Alo[kt][half * 2 + 1]);
        }
    }
}

__global__ __launch_bounds__(256, 1) void conv_kernel(
    const float* __restrict__ x, float* __restrict__ out)
{
    extern __shared__ __align__(16) char smem[];
    const float* bsm = (const float*)(smem + 212992);

    const int tid = threadIdx.x;
    const int w = tid >> 5, lane = tid & 31;
    const int gid = lane >> 2, tig = lane & 3;
    const int b  = blockIdx.x / 9;
    const int cs = blockIdx.x % 9;

    // stage all fragment-ordered weights (212992 B) + biases (2 KB)
    {
        const uint4* src = (const uint4*)(g_wb + (size_t)b * WS);
        uint4* dst = (uint4*)smem;
        for (int i = tid; i < 13312; i += 256) dst[i] = src[i];
        const float4* bsrc = (const float4*)(g_bias + b * 512);
        float4* bdst = (float4*)(smem + 212992);
        if (tid < 128) bdst[tid] = bsrc[tid];
    }
    __syncthreads();

    const float* xb = x + (size_t)b * FIN * HW;
    float* ob = out + (size_t)b * FOUT * HW;

    float    D[16][4];
    uint32_t Xhi[4][4], Xlo[4][4];
    uint32_t Ahi[8][4], Alo[8][4];

    for (int t = cs; t < 128; t += 9) {
        const int p0 = t * 128;
        const int px_lo = p0 + w * 16 + gid;
        const int px_hi = px_lo + 8;

        // ---- load x as A fragments (bf16 hi/lo) ----
#pragma unroll
        for (int kt = 0; kt < 4; kt++) {
            const float* xp = xb + (size_t)(kt * 16 + tig * 2) * HW;
            float e00 = xp[px_lo],          e01 = xp[HW + px_lo];
            float e10 = xp[px_hi],          e11 = xp[HW + px_hi];
            float e20 = xp[8 * HW + px_lo], e21 = xp[9 * HW + px_lo];
            float e30 = xp[8 * HW + px_hi], e31 = xp[9 * HW + px_hi];
            split2(e00, e01, Xhi[kt][0], Xlo[kt][0]);
            split2(e10, e11, Xhi[kt][1], Xlo[kt][1]);
            split2(e20, e21, Xhi[kt][2], Xlo[kt][2]);
            split2(e30, e31, Xhi[kt][3], Xlo[kt][3]);
        }

        // ---- layer in: D = Win @ x ----
        layer_mma<4, 16, true>(D, Xhi, Xlo, smem, WIN_HI * 2, (WIN_HI + 8192) * 2, lane);
        epi_relu_split<8>(D, Ahi, Alo, bsm + 0, tig);

        // ---- layer mida ----
        layer_mma<8, 16, true>(D, Ahi, Alo, smem, WMIDA_HI * 2, (WMIDA_HI + 16384) * 2, lane);
        epi_relu_split<8>(D, Ahi, Alo, bsm + 128, tig);

        // ---- layer midb ----
        layer_mma<8, 16, true>(D, Ahi, Alo, smem, WMIDB_HI * 2, (WMIDB_HI + 16384) * 2, lane);
        epi_relu_split<8>(D, Ahi, Alo, bsm + 256, tig);

        // ---- out: D = Wout @ h + Wshort @ x ----
        layer_mma<8, 8, true >(D, Ahi, Alo, smem, WOUT_HI * 2, (WOUT_HI + 8192) * 2, lane);
        layer_mma<4, 8, false>(D, Xhi, Xlo, smem, WSH_HI * 2,  (WSH_HI + 4096) * 2, lane);

        // ---- final epilogue: + b_out + b_short -> gmem ----
#pragma unroll
        for (int nt = 0; nt < 8; nt++) {
            int ch = nt * 8 + tig * 2;
            float b0 = bsm[384 + ch]     + bsm[448 + ch];
            float b1 = bsm[384 + ch + 1] + bsm[448 + ch + 1];
            float* op = ob + (size_t)ch * HW;
            op[px_lo]      = D[nt][0] + b0;
            op[HW + px_lo] = D[nt][1] + b1;
            op[px_hi]      = D[nt][2] + b0;
            op[HW + px_hi] = D[nt][3] + b1;
        }
    }
}

// ============================================================
extern "C" void kernel_launch(void* const* d_in, const int* in_sizes, int n_in,
                              void* d_out, int out_size)
{
    (void)in_sizes; (void)n_in; (void)out_size;
    const float* x    = (const float*)d_in[0];
    const float* lat  = (const float*)d_in[1];
    const float* W    = (const float*)d_in[2];
    const float* bias = (const float*)d_in[3];
    float* out = (float*)d_out;

    hyper_kernel<<<KTOT / 256, 256>>>(lat, W, bias);

    cudaFuncSetAttribute(conv_kernel,
                         cudaFuncAttributeMaxDynamicSharedMemorySize, 215040);
    conv_kernel<<<16 * 9, 256, 215040>>>(x, out);
}